// round 10
// baseline (speedup 1.0000x reference)
#include <cuda_runtime.h>
#include <cuda_bf16.h>
#include <cstdint>

#define BB   64
#define CC   256
#define NTOK 1600
#define VQ   25
#define HH   8
#define HD   32
#define RR   200
#define RP   256

typedef __nv_bfloat16 bf;

// -------- device scratch (allocation-free rule; zero-init at load) --------
__device__ __align__(16) bf    g_Qeh[BB * RP * CC];   // pad rows 200..255 stay 0
__device__ __align__(16) bf    g_Qel[BB * RP * CC];
__device__ __align__(16) float g_S  [BB * RP * NTOK]; // scores -> probs in place
__device__ __align__(16) float g_Y  [BB * RP * CC];
__device__ __align__(16) float g_We [HH * CC * CC];

// ==================== PTX helpers (baseline ISA only) ====================
__device__ __forceinline__ uint32_t smem_u32(const void* p) {
    uint32_t a;
    asm("{ .reg .u64 t; cvta.to.shared.u64 t, %1; cvt.u32.u64 %0, t; }" : "=r"(a) : "l"(p));
    return a;
}
__device__ __forceinline__ void ldsm4(uint32_t* r, uint32_t a) {
    asm volatile("ldmatrix.sync.aligned.m8n8.x4.shared.b16 {%0,%1,%2,%3}, [%4];"
                 : "=r"(r[0]), "=r"(r[1]), "=r"(r[2]), "=r"(r[3]) : "r"(a));
}
__device__ __forceinline__ void ldsm2(uint32_t* r, uint32_t a) {
    asm volatile("ldmatrix.sync.aligned.m8n8.x2.shared.b16 {%0,%1}, [%2];"
                 : "=r"(r[0]), "=r"(r[1]) : "r"(a));
}
__device__ __forceinline__ void ldsm2t(uint32_t* r, uint32_t a) {
    asm volatile("ldmatrix.sync.aligned.m8n8.x2.trans.shared.b16 {%0,%1}, [%2];"
                 : "=r"(r[0]), "=r"(r[1]) : "r"(a));
}
__device__ __forceinline__ void mma_bf16(float* c, const uint32_t* a, const uint32_t* b) {
    asm volatile("mma.sync.aligned.m16n8k16.row.col.f32.bf16.bf16.f32 "
                 "{%0,%1,%2,%3}, {%4,%5,%6,%7}, {%8,%9}, {%0,%1,%2,%3};"
                 : "+f"(c[0]), "+f"(c[1]), "+f"(c[2]), "+f"(c[3])
                 : "r"(a[0]), "r"(a[1]), "r"(a[2]), "r"(a[3]), "r"(b[0]), "r"(b[1]));
}
__device__ __forceinline__ void cp16(uint32_t d, const void* g) {
    asm volatile("cp.async.cg.shared.global [%0], [%1], 16;" :: "r"(d), "l"(g) : "memory");
}
#define CP_COMMIT() asm volatile("cp.async.commit_group;" ::: "memory")
#define CP_WAIT(n)  asm volatile("cp.async.wait_group %0;" :: "n"(n) : "memory")

__device__ __forceinline__ void split_bf(float v, bf& h, bf& l) {
    h = __float2bfloat16(v);
    l = __float2bfloat16(v - __bfloat162float(h));
}
__device__ __forceinline__ void split4(float4 v, uint2& hi, uint2& lo) {
    bf h0, l0, h1, l1, h2, l2, h3, l3;
    split_bf(v.x, h0, l0); split_bf(v.y, h1, l1);
    split_bf(v.z, h2, l2); split_bf(v.w, h3, l3);
    __nv_bfloat162 hh0(h0, h1), hh1(h2, h3), ll0(l0, l1), ll1(l2, l3);
    hi.x = *(uint32_t*)&hh0; hi.y = *(uint32_t*)&hh1;
    lo.x = *(uint32_t*)&ll0; lo.y = *(uint32_t*)&ll1;
}

// ==================== GEMM1: S[b][r][n] = Qe @ X (contract c=256) ====================
// Block 128(r) x 160(n); warps 2(m) x 4(n) -> warp tile 64 x 40.
// A: split bf16 from g_Qe* via cp.async (swizzled). B: fp32 X via cp.async raw,
// split->padded bf16 in-kernel. Double-buffered stages; conv buffer single.
#define B1P   336                 // converted B row pitch (bytes)
#define RB1P  656                 // raw fp32 B row pitch (bytes): 160*4 + 16
#define STG1  (32768 + 64 * RB1P) // 74752
__global__ __launch_bounds__(256, 1)
void gemm1_mma(const float* __restrict__ Xf) {
    extern __shared__ char smem[];
    constexpr int A_HI = 0, A_LO = 16384, RAWB = 32768;
    constexpr int BC_HI = 2 * STG1, BC_LO = 2 * STG1 + 64 * B1P;
    const int b = blockIdx.z, r0 = blockIdx.y * 128, n0 = blockIdx.x * 160;
    const int tid = threadIdx.x, lane = tid & 31, wid = tid >> 5;
    const int wm = wid >> 2, wn = wid & 3;
    const uint32_t sb = smem_u32(smem);

    float acc[4][5][4];
#pragma unroll
    for (int i = 0; i < 4; i++)
#pragma unroll
        for (int j = 0; j < 5; j++)
#pragma unroll
            for (int k = 0; k < 4; k++) acc[i][j][k] = 0.f;

    const bf* Ah = g_Qeh + ((long long)b * RP + r0) * CC;
    const bf* Al = g_Qel + ((long long)b * RP + r0) * CC;
    const float* Bx = Xf + (long long)b * CC * NTOK + n0;

    auto load = [&](int kc, int st) {
        const uint32_t base = sb + st * STG1;
#pragma unroll
        for (int it = 0; it < 4; it++) {
            int idx = tid + it * 256;
            int r = idx >> 3, c = idx & 7;
            uint32_t off = (uint32_t)(r * 128 + c * 16);
            off ^= (off >> 3) & 0x70;
            const long long go = (long long)r * CC + kc * 64 + c * 8;
            cp16(base + A_HI + off, Ah + go);
            cp16(base + A_LO + off, Al + go);
        }
#pragma unroll
        for (int it = 0; it < 10; it++) {
            int idx = tid + it * 256;
            int r = idx / 40, c16 = idx % 40;
            cp16(base + RAWB + r * RB1P + c16 * 16,
                 Bx + (long long)(kc * 64 + r) * NTOK + c16 * 4);
        }
    };

    load(0, 0);
    CP_COMMIT();

    for (int kc = 0; kc < 4; kc++) {
        if (kc + 1 < 4) {
            load(kc + 1, (kc + 1) & 1);
            CP_COMMIT();
            CP_WAIT(1);
        } else {
            CP_WAIT(0);
        }
        __syncthreads();

        // convert raw fp32 B -> bf16 hi/lo (padded rows, no swizzle)
        const char* rbase = smem + (kc & 1) * STG1 + RAWB;
#pragma unroll
        for (int it = 0; it < 10; it++) {
            int idx = tid + it * 256;
            int r = idx / 40, c4 = idx % 40;
            float4 v = *(const float4*)(rbase + r * RB1P + c4 * 16);
            uint2 hi, lo; split4(v, hi, lo);
            *(uint2*)(smem + BC_HI + r * B1P + c4 * 8) = hi;
            *(uint2*)(smem + BC_LO + r * B1P + c4 * 8) = lo;
        }
        __syncthreads();

        const uint32_t abase = sb + (kc & 1) * STG1;
#pragma unroll
        for (int ks = 0; ks < 4; ks++) {
            uint32_t ah[4][4], al[4][4], bh[5][2], bl[5][2];
            const uint32_t kbyte = ks * 32 + (lane >> 4) * 16;
#pragma unroll
            for (int mf = 0; mf < 4; mf++) {
                uint32_t row = wm * 64 + mf * 16 + (lane & 15);
                uint32_t off = row * 128 + kbyte;
                off ^= (off >> 3) & 0x70;
                ldsm4(ah[mf], abase + A_HI + off);
                ldsm4(al[mf], abase + A_LO + off);
            }
            const uint32_t crow = ks * 16 + (lane & 15);
#pragma unroll
            for (int nf = 0; nf < 5; nf++) {
                uint32_t off = crow * B1P + (wn * 40 + nf * 8) * 2;
                ldsm2t(bh[nf], sb + BC_HI + off);
                ldsm2t(bl[nf], sb + BC_LO + off);
            }
            // term-major: consecutive MMAs hit different accumulators (RAW dist 20)
#pragma unroll
            for (int mf = 0; mf < 4; mf++)
#pragma unroll
                for (int nf = 0; nf < 5; nf++) mma_bf16(acc[mf][nf], ah[mf], bh[nf]);
#pragma unroll
            for (int mf = 0; mf < 4; mf++)
#pragma unroll
                for (int nf = 0; nf < 5; nf++) mma_bf16(acc[mf][nf], ah[mf], bl[nf]);
#pragma unroll
            for (int mf = 0; mf < 4; mf++)
#pragma unroll
                for (int nf = 0; nf < 5; nf++) mma_bf16(acc[mf][nf], al[mf], bh[nf]);
        }
        __syncthreads();
    }

    float* Out = g_S + ((long long)b * RP + r0 + wm * 64) * NTOK + n0 + wn * 40;
    const int rr = lane >> 2, cc2 = (lane & 3) * 2;
#pragma unroll
    for (int mf = 0; mf < 4; mf++)
#pragma unroll
        for (int nf = 0; nf < 5; nf++) {
            float* o = Out + (long long)(mf * 16 + rr) * NTOK + nf * 8 + cc2;
            *(float2*)o = make_float2(acc[mf][nf][0], acc[mf][nf][1]);
            *(float2*)(o + 8LL * NTOK) = make_float2(acc[mf][nf][2], acc[mf][nf][3]);
        }
}

// ==================== GEMM2: Y[b][r][c] = P @ X^T (contract n=1600) ====================
// Block 128(r) x 128(c); warps 2(m) x 4(n) -> warp tile 64 x 32.
// A = P fp32 (from g_S, softmaxed in place), B = X fp32; both split in-kernel.
#define R2P   272                 // raw fp32 row pitch: 64*4 + 16
#define STG2  (2 * 128 * R2P)     // 69632 (A raw + B raw)
__global__ __launch_bounds__(256, 1)
void gemm2_mma(const float* __restrict__ Xf) {
    extern __shared__ char smem[];
    constexpr int A_RAW = 0, B_RAW = 128 * R2P;
    constexpr int CV = 2 * STG2;  // 139264
    constexpr int A_HI = CV, A_LO = CV + 16384, B_HI = CV + 32768, B_LO = CV + 49152;
    const int b = blockIdx.z, r0 = blockIdx.y * 128, c0 = blockIdx.x * 128;
    const int tid = threadIdx.x, lane = tid & 31, wid = tid >> 5;
    const int wm = wid >> 2, wn = wid & 3;
    const uint32_t sb = smem_u32(smem);

    float acc[4][4][4];
#pragma unroll
    for (int i = 0; i < 4; i++)
#pragma unroll
        for (int j = 0; j < 4; j++)
#pragma unroll
            for (int k = 0; k < 4; k++) acc[i][j][k] = 0.f;

    const float* Ap = g_S + ((long long)b * RP + r0) * NTOK;
    const float* Bx = Xf + ((long long)b * CC + c0) * NTOK;

    auto load = [&](int kc, int st) {
        const uint32_t base = sb + st * STG2;
#pragma unroll
        for (int it = 0; it < 8; it++) {
            int idx = tid + it * 256;
            int r = idx >> 4, c16 = idx & 15;
            const long long go = (long long)r * NTOK + kc * 64 + c16 * 4;
            cp16(base + A_RAW + r * R2P + c16 * 16, Ap + go);
            cp16(base + B_RAW + r * R2P + c16 * 16, Bx + go);
        }
    };

    load(0, 0);
    CP_COMMIT();

    for (int kc = 0; kc < 25; kc++) {
        if (kc + 1 < 25) {
            load(kc + 1, (kc + 1) & 1);
            CP_COMMIT();
            CP_WAIT(1);
        } else {
            CP_WAIT(0);
        }
        __syncthreads();

        // convert raw fp32 A,B -> swizzled bf16 hi/lo
        const char* rbase = smem + (kc & 1) * STG2;
#pragma unroll
        for (int it = 0; it < 8; it++) {
            int idx = tid + it * 256;
            int r = idx >> 4, c4 = idx & 15;
            float4 av = *(const float4*)(rbase + A_RAW + r * R2P + c4 * 16);
            float4 bv = *(const float4*)(rbase + B_RAW + r * R2P + c4 * 16);
            uint32_t off = (uint32_t)(r * 128 + c4 * 8);
            off ^= (off >> 3) & 0x70;
            uint2 hi, lo;
            split4(av, hi, lo);
            *(uint2*)(smem + A_HI + off) = hi;
            *(uint2*)(smem + A_LO + off) = lo;
            split4(bv, hi, lo);
            *(uint2*)(smem + B_HI + off) = hi;
            *(uint2*)(smem + B_LO + off) = lo;
        }
        __syncthreads();

#pragma unroll
        for (int ks = 0; ks < 4; ks++) {
            uint32_t ah[4][4], al[4][4], bh[4][2], bl[4][2];
            const uint32_t kbyte = ks * 32 + (lane >> 4) * 16;
#pragma unroll
            for (int mf = 0; mf < 4; mf++) {
                uint32_t row = wm * 64 + mf * 16 + (lane & 15);
                uint32_t off = row * 128 + kbyte;
                off ^= (off >> 3) & 0x70;
                ldsm4(ah[mf], sb + A_HI + off);
                ldsm4(al[mf], sb + A_LO + off);
            }
            const uint32_t kb2 = ks * 32 + ((lane & 15) >> 3) * 16;
#pragma unroll
            for (int nf = 0; nf < 4; nf++) {
                uint32_t row = wn * 32 + nf * 8 + (lane & 7);
                uint32_t off = row * 128 + kb2;
                off ^= (off >> 3) & 0x70;
                ldsm2(bh[nf], sb + B_HI + off);
                ldsm2(bl[nf], sb + B_LO + off);
            }
            // term-major MMA issue
#pragma unroll
            for (int mf = 0; mf < 4; mf++)
#pragma unroll
                for (int nf = 0; nf < 4; nf++) mma_bf16(acc[mf][nf], ah[mf], bh[nf]);
#pragma unroll
            for (int mf = 0; mf < 4; mf++)
#pragma unroll
                for (int nf = 0; nf < 4; nf++) mma_bf16(acc[mf][nf], ah[mf], bl[nf]);
#pragma unroll
            for (int mf = 0; mf < 4; mf++)
#pragma unroll
                for (int nf = 0; nf < 4; nf++) mma_bf16(acc[mf][nf], al[mf], bh[nf]);
        }
        __syncthreads();
    }

    float* Out = g_Y + ((long long)b * RP + r0 + wm * 64) * CC + c0 + wn * 32;
    const int rr = lane >> 2, cc2 = (lane & 3) * 2;
#pragma unroll
    for (int mf = 0; mf < 4; mf++)
#pragma unroll
        for (int nf = 0; nf < 4; nf++) {
            float* o = Out + (long long)(mf * 16 + rr) * CC + nf * 8 + cc2;
            *(float2*)o = make_float2(acc[mf][nf][0], acc[mf][nf][1]);
            *(float2*)(o + 8LL * CC) = make_float2(acc[mf][nf][2], acc[mf][nf][3]);
        }
}

// ==================== support kernels ====================

// Weff[h][co][c] = sum_d proj_w[co][h*32+d] * v_w[h*32+d][c]
__global__ __launch_bounds__(256)
void weff_kernel(const float* __restrict__ pw, const float* __restrict__ vw) {
    const int h = blockIdx.x, co0 = blockIdx.y * 32, c = threadIdx.x;
    float vv[HD];
#pragma unroll
    for (int d = 0; d < HD; d++) vv[d] = vw[(h * HD + d) * CC + c];
    for (int i = 0; i < 32; i++) {
        const int co = co0 + i;
        float a = 0.f;
#pragma unroll
        for (int d = 0; d < HD; d++) a += pw[co * CC + h * HD + d] * vv[d];
        g_We[(h * CC + co) * CC + c] = a;
    }
}

// Qeff (bf16 hi/lo); pad rows never written (stay zero).
__global__ __launch_bounds__(256)
void qeff_kernel(const float* __restrict__ x_cls, const float* __restrict__ qw,
                 const float* __restrict__ kw, const float* __restrict__ temp) {
    const int b = blockIdx.x, t = threadIdx.x;
    __shared__ float buf[6528];

    for (int i = t; i < CC * VQ; i += 256) buf[i] = x_cls[b * CC * VQ + i];
    __syncthreads();

    float acc[VQ];
#pragma unroll
    for (int v = 0; v < VQ; v++) acc[v] = 0.f;
    const float* wrow = qw + t * CC;
    for (int c2 = 0; c2 < CC; c2++) {
        float w = wrow[c2];
#pragma unroll
        for (int v = 0; v < VQ; v++) acc[v] += w * buf[c2 * VQ + v];
    }
    const float s = temp[t >> 5] * 0.17677669529663687f;
    __syncthreads();
#pragma unroll
    for (int v = 0; v < VQ; v++) buf[v * 260 + t] = acc[v] * s;
    __syncthreads();

    for (int h = 0; h < HH; h++) {
        float kv[HD];
#pragma unroll
        for (int d = 0; d < HD; d++) kv[d] = kw[(h * HD + d) * CC + t];
        for (int v = 0; v < VQ; v++) {
            float a = 0.f;
#pragma unroll
            for (int d = 0; d < HD; d++) a += buf[v * 260 + h * HD + d] * kv[d];
            bf hi, lo; split_bf(a, hi, lo);
            const long long idx = ((long long)b * RP + h * VQ + v) * CC + t;
            g_Qeh[idx] = hi;
            g_Qel[idx] = lo;
        }
    }
}

// Row softmax over g_S rows r<200, IN PLACE (fp32 probs).
__global__ __launch_bounds__(256)
void softmax_kernel() {
    const int wid = threadIdx.x >> 5, lane = threadIdx.x & 31;
    const int r = blockIdx.x * 8 + wid, b = blockIdx.y;
    float* p = g_S + ((long long)b * RP + r) * NTOK;

    float v[50];
    float mx = -1e30f;
#pragma unroll
    for (int i = 0; i < 50; i++) { v[i] = p[i * 32 + lane]; mx = fmaxf(mx, v[i]); }
#pragma unroll
    for (int o = 16; o; o >>= 1) mx = fmaxf(mx, __shfl_xor_sync(0xffffffffu, mx, o));
    float s = 0.f;
#pragma unroll
    for (int i = 0; i < 50; i++) { float e = __expf(v[i] - mx); v[i] = e; s += e; }
#pragma unroll
    for (int o = 16; o; o >>= 1) s += __shfl_xor_sync(0xffffffffu, s, o);
    const float inv = 1.f / s;
#pragma unroll
    for (int i = 0; i < 50; i++) p[i * 32 + lane] = v[i] * inv;
}

// Final: out[b][co][v] = proj_b[co] + sum_h sum_c We[h][co][c] * Y[b][h*25+v][c]
__global__ __launch_bounds__(256)
void final_kernel(const float* __restrict__ pb, float* __restrict__ out) {
    const int b = blockIdx.x, gy = blockIdx.y, t = threadIdx.x;
    __shared__ float ys[256 * 27 + 32];

    const int nv = (gy == 0) ? 7 : 6;
    float acc[7];
    const float bias = pb[t];
#pragma unroll
    for (int k = 0; k < 7; k++) acc[k] = bias;

    for (int h = 0; h < HH; h++) {
        __syncthreads();
        for (int i = t; i < VQ * CC; i += 256) {
            int v = i >> 8, c = i & 255;
            ys[c * 27 + v] = g_Y[((long long)b * RP + h * VQ + v) * CC + c];
        }
        __syncthreads();
        const float* we = g_We + (h * CC + t) * CC;
        for (int c = 0; c < CC; c++) {
            float w = we[c];
#pragma unroll
            for (int k = 0; k < 7; k++)
                acc[k] += w * ys[c * 27 + gy + 4 * k];
        }
    }
    for (int k = 0; k < nv; k++)
        out[b * (CC * VQ) + t * VQ + gy + 4 * k] = acc[k];
}

// ---------------------------------------------------------------
extern "C" void kernel_launch(void* const* d_in, const int* in_sizes, int n_in,
                              void* d_out, int out_size) {
    (void)in_sizes; (void)n_in; (void)out_size;
    const float* x_cls   = (const float*)d_in[0];
    const float* x_patch = (const float*)d_in[1];
    const float* q_w     = (const float*)d_in[2];
    const float* k_w     = (const float*)d_in[3];
    const float* v_w     = (const float*)d_in[4];
    const float* temp    = (const float*)d_in[5];
    const float* proj_w  = (const float*)d_in[6];
    const float* proj_b  = (const float*)d_in[7];
    float* out = (float*)d_out;

    const int SMEM1 = 2 * STG1 + 2 * 64 * B1P;      // 192512
    const int SMEM2 = 2 * STG2 + 4 * 16384;         // 204800
    cudaFuncSetAttribute(gemm1_mma, cudaFuncAttributeMaxDynamicSharedMemorySize, SMEM1);
    cudaFuncSetAttribute(gemm2_mma, cudaFuncAttributeMaxDynamicSharedMemorySize, SMEM2);

    weff_kernel<<<dim3(HH, 8), 256>>>(proj_w, v_w);
    qeff_kernel<<<BB, 256>>>(x_cls, q_w, k_w, temp);
    gemm1_mma<<<dim3(10, 2, BB), 256, SMEM1>>>(x_patch);
    softmax_kernel<<<dim3(RR / 8, BB), 256>>>();
    gemm2_mma<<<dim3(2, 2, BB), 256, SMEM2>>>(x_patch);
    final_kernel<<<dim3(BB, 4), 256>>>(proj_b, out);
}

// round 11
// speedup vs baseline: 1.0821x; 1.0821x over previous
#include <cuda_runtime.h>
#include <cuda_bf16.h>
#include <cstdint>

#define BB   64
#define CC   256
#define NTOK 1600
#define VQ   25
#define HH   8
#define HD   32
#define RR   200
#define RP   256

typedef __nv_bfloat16 bf;

// -------- device scratch (allocation-free rule; zero-init at load) --------
__device__ __align__(16) bf    g_Qeh[BB * RP * CC];   // pad rows 200..255 stay 0
__device__ __align__(16) bf    g_Qel[BB * RP * CC];
__device__ __align__(16) bf    g_Xh [BB * CC * NTOK];
__device__ __align__(16) bf    g_Xl [BB * CC * NTOK];
__device__ __align__(16) bf    g_Ph [BB * RP * NTOK]; // pad rows stay 0
__device__ __align__(16) bf    g_Pl [BB * RP * NTOK];
__device__ __align__(16) float g_S  [BB * RP * NTOK];
__device__ __align__(16) float g_Y  [BB * RP * CC];
__device__ __align__(16) float g_We [HH * CC * CC];

// ==================== PTX helpers (baseline ISA only) ====================
__device__ __forceinline__ uint32_t smem_u32(const void* p) {
    uint32_t a;
    asm("{ .reg .u64 t; cvta.to.shared.u64 t, %1; cvt.u32.u64 %0, t; }" : "=r"(a) : "l"(p));
    return a;
}
__device__ __forceinline__ void ldsm4(uint32_t* r, uint32_t a) {
    asm volatile("ldmatrix.sync.aligned.m8n8.x4.shared.b16 {%0,%1,%2,%3}, [%4];"
                 : "=r"(r[0]), "=r"(r[1]), "=r"(r[2]), "=r"(r[3]) : "r"(a));
}
__device__ __forceinline__ void ldsm2(uint32_t* r, uint32_t a) {
    asm volatile("ldmatrix.sync.aligned.m8n8.x2.shared.b16 {%0,%1}, [%2];"
                 : "=r"(r[0]), "=r"(r[1]) : "r"(a));
}
__device__ __forceinline__ void ldsm2t(uint32_t* r, uint32_t a) {
    asm volatile("ldmatrix.sync.aligned.m8n8.x2.trans.shared.b16 {%0,%1}, [%2];"
                 : "=r"(r[0]), "=r"(r[1]) : "r"(a));
}
__device__ __forceinline__ void mma_bf16(float* c, const uint32_t* a, const uint32_t* b) {
    asm volatile("mma.sync.aligned.m16n8k16.row.col.f32.bf16.bf16.f32 "
                 "{%0,%1,%2,%3}, {%4,%5,%6,%7}, {%8,%9}, {%0,%1,%2,%3};"
                 : "+f"(c[0]), "+f"(c[1]), "+f"(c[2]), "+f"(c[3])
                 : "r"(a[0]), "r"(a[1]), "r"(a[2]), "r"(a[3]), "r"(b[0]), "r"(b[1]));
}
__device__ __forceinline__ void cp16(uint32_t d, const void* g) {
    asm volatile("cp.async.cg.shared.global [%0], [%1], 16;" :: "r"(d), "l"(g) : "memory");
}
#define CP_COMMIT() asm volatile("cp.async.commit_group;" ::: "memory")
#define CP_WAIT(n)  asm volatile("cp.async.wait_group %0;" :: "n"(n) : "memory")

__device__ __forceinline__ void split_bf(float v, bf& h, bf& l) {
    h = __float2bfloat16(v);
    l = __float2bfloat16(v - __bfloat162float(h));
}

// ==================== GEMM1: S[b][r][n] = Qe @ X (contract c=256) ====================
// Block 128(r) x 64(n); warps 4(m) x 2(n) -> warp tile 32 x 32 (acc=32 regs).
// 2 CTAs/SM. cp.async double-buffered.
#define B1P  144                       // padded B row bytes: 64*2 + 16
#define STG1 (32768 + 2 * 64 * B1P)    // 51200
__global__ __launch_bounds__(256, 2)
void gemm1_mma() {
    extern __shared__ char smem[];
    constexpr int A_HI = 0, A_LO = 16384, B_HI = 32768, B_LO = 32768 + 64 * B1P;
    const int b = blockIdx.z, r0 = blockIdx.y * 128, n0 = blockIdx.x * 64;
    const int tid = threadIdx.x, lane = tid & 31, wid = tid >> 5;
    const int wm = wid >> 1, wn = wid & 1;
    const uint32_t sb = smem_u32(smem);

    float acc[2][4][4];
#pragma unroll
    for (int i = 0; i < 2; i++)
#pragma unroll
        for (int j = 0; j < 4; j++)
#pragma unroll
            for (int k = 0; k < 4; k++) acc[i][j][k] = 0.f;

    const bf* Ah = g_Qeh + ((long long)b * RP + r0) * CC;
    const bf* Al = g_Qel + ((long long)b * RP + r0) * CC;
    const bf* Bh = g_Xh + (long long)b * CC * NTOK + n0;
    const bf* Bl = g_Xl + (long long)b * CC * NTOK + n0;

    auto load = [&](int kc, int st) {
        const uint32_t base = sb + st * STG1;
#pragma unroll
        for (int it = 0; it < 4; it++) {
            int idx = tid + it * 256;
            int r = idx >> 3, c = idx & 7;
            uint32_t off = (uint32_t)(r * 128 + c * 16);
            off ^= (off >> 3) & 0x70;
            const long long go = (long long)r * CC + kc * 64 + c * 8;
            cp16(base + A_HI + off, Ah + go);
            cp16(base + A_LO + off, Al + go);
        }
#pragma unroll
        for (int it = 0; it < 2; it++) {
            int idx = tid + it * 256;
            int r = idx >> 3, c8 = idx & 7;
            const long long go = (long long)(kc * 64 + r) * NTOK + c8 * 8;
            cp16(base + B_HI + r * B1P + c8 * 16, Bh + go);
            cp16(base + B_LO + r * B1P + c8 * 16, Bl + go);
        }
    };

    load(0, 0);
    CP_COMMIT();

    for (int kc = 0; kc < 4; kc++) {
        if (kc + 1 < 4) {
            load(kc + 1, (kc + 1) & 1);
            CP_COMMIT();
            CP_WAIT(1);
        } else {
            CP_WAIT(0);
        }
        __syncthreads();

        const uint32_t base = sb + (kc & 1) * STG1;
#pragma unroll
        for (int ks = 0; ks < 4; ks++) {
            uint32_t ah[2][4], al[2][4], bh[4][2], bl[4][2];
            const uint32_t kbyte = ks * 32 + (lane >> 4) * 16;
#pragma unroll
            for (int mf = 0; mf < 2; mf++) {
                uint32_t row = wm * 32 + mf * 16 + (lane & 15);
                uint32_t off = row * 128 + kbyte;
                off ^= (off >> 3) & 0x70;
                ldsm4(ah[mf], base + A_HI + off);
                ldsm4(al[mf], base + A_LO + off);
            }
            const uint32_t crow = ks * 16 + (lane & 15);
#pragma unroll
            for (int nf = 0; nf < 4; nf++) {
                uint32_t off = crow * B1P + (wn * 32 + nf * 8) * 2;
                ldsm2t(bh[nf], base + B_HI + off);
                ldsm2t(bl[nf], base + B_LO + off);
            }
            // term-major: consecutive MMAs hit different accumulators
#pragma unroll
            for (int mf = 0; mf < 2; mf++)
#pragma unroll
                for (int nf = 0; nf < 4; nf++) mma_bf16(acc[mf][nf], ah[mf], bh[nf]);
#pragma unroll
            for (int mf = 0; mf < 2; mf++)
#pragma unroll
                for (int nf = 0; nf < 4; nf++) mma_bf16(acc[mf][nf], ah[mf], bl[nf]);
#pragma unroll
            for (int mf = 0; mf < 2; mf++)
#pragma unroll
                for (int nf = 0; nf < 4; nf++) mma_bf16(acc[mf][nf], al[mf], bh[nf]);
        }
        __syncthreads();
    }

    float* Out = g_S + ((long long)b * RP + r0 + wm * 32) * NTOK + n0 + wn * 32;
    const int rr = lane >> 2, cc2 = (lane & 3) * 2;
#pragma unroll
    for (int mf = 0; mf < 2; mf++)
#pragma unroll
        for (int nf = 0; nf < 4; nf++) {
            float* o = Out + (long long)(mf * 16 + rr) * NTOK + nf * 8 + cc2;
            *(float2*)o = make_float2(acc[mf][nf][0], acc[mf][nf][1]);
            *(float2*)(o + 8LL * NTOK) = make_float2(acc[mf][nf][2], acc[mf][nf][3]);
        }
}

// ==================== GEMM2: Y[b][r][c] = P @ X^T (contract n=1600) ====================
// Block 128(r) x 64(c); warps 4(m) x 2(n) -> warp tile 32 x 32. Both operands K-major.
#define STG2 49152
__global__ __launch_bounds__(256, 2)
void gemm2_mma() {
    extern __shared__ char smem[];
    constexpr int A_HI = 0, A_LO = 16384, B_HI = 32768, B_LO = 40960;
    const int b = blockIdx.z, r0 = blockIdx.y * 128, c0 = blockIdx.x * 64;
    const int tid = threadIdx.x, lane = tid & 31, wid = tid >> 5;
    const int wm = wid >> 1, wn = wid & 1;
    const uint32_t sb = smem_u32(smem);

    float acc[2][4][4];
#pragma unroll
    for (int i = 0; i < 2; i++)
#pragma unroll
        for (int j = 0; j < 4; j++)
#pragma unroll
            for (int k = 0; k < 4; k++) acc[i][j][k] = 0.f;

    const bf* Ah = g_Ph + ((long long)b * RP + r0) * NTOK;
    const bf* Al = g_Pl + ((long long)b * RP + r0) * NTOK;
    const bf* Bh = g_Xh + ((long long)b * CC + c0) * NTOK;
    const bf* Bl = g_Xl + ((long long)b * CC + c0) * NTOK;

    auto load = [&](int kc, int st) {
        const uint32_t base = sb + st * STG2;
#pragma unroll
        for (int it = 0; it < 4; it++) {
            int idx = tid + it * 256;
            int r = idx >> 3, c = idx & 7;
            uint32_t off = (uint32_t)(r * 128 + c * 16);
            off ^= (off >> 3) & 0x70;
            const long long ga = (long long)r * NTOK + kc * 64 + c * 8;
            cp16(base + A_HI + off, Ah + ga);
            cp16(base + A_LO + off, Al + ga);
        }
#pragma unroll
        for (int it = 0; it < 2; it++) {
            int idx = tid + it * 256;
            int r = idx >> 3, c = idx & 7;
            uint32_t off = (uint32_t)(r * 128 + c * 16);
            off ^= (off >> 3) & 0x70;
            const long long gb = (long long)r * NTOK + kc * 64 + c * 8;
            cp16(base + B_HI + off, Bh + gb);
            cp16(base + B_LO + off, Bl + gb);
        }
    };

    load(0, 0);
    CP_COMMIT();

    for (int kc = 0; kc < 25; kc++) {
        if (kc + 1 < 25) {
            load(kc + 1, (kc + 1) & 1);
            CP_COMMIT();
            CP_WAIT(1);
        } else {
            CP_WAIT(0);
        }
        __syncthreads();

        const uint32_t base = sb + (kc & 1) * STG2;
#pragma unroll
        for (int ks = 0; ks < 4; ks++) {
            uint32_t ah[2][4], al[2][4], bh[4][2], bl[4][2];
            const uint32_t kbyte = ks * 32 + (lane >> 4) * 16;
#pragma unroll
            for (int mf = 0; mf < 2; mf++) {
                uint32_t row = wm * 32 + mf * 16 + (lane & 15);
                uint32_t off = row * 128 + kbyte;
                off ^= (off >> 3) & 0x70;
                ldsm4(ah[mf], base + A_HI + off);
                ldsm4(al[mf], base + A_LO + off);
            }
            const uint32_t kb2 = ks * 32 + ((lane & 15) >> 3) * 16;
#pragma unroll
            for (int nf = 0; nf < 4; nf++) {
                uint32_t row = wn * 32 + nf * 8 + (lane & 7);
                uint32_t off = row * 128 + kb2;
                off ^= (off >> 3) & 0x70;
                ldsm2(bh[nf], base + B_HI + off);
                ldsm2(bl[nf], base + B_LO + off);
            }
            // term-major MMA issue
#pragma unroll
            for (int mf = 0; mf < 2; mf++)
#pragma unroll
                for (int nf = 0; nf < 4; nf++) mma_bf16(acc[mf][nf], ah[mf], bh[nf]);
#pragma unroll
            for (int mf = 0; mf < 2; mf++)
#pragma unroll
                for (int nf = 0; nf < 4; nf++) mma_bf16(acc[mf][nf], ah[mf], bl[nf]);
#pragma unroll
            for (int mf = 0; mf < 2; mf++)
#pragma unroll
                for (int nf = 0; nf < 4; nf++) mma_bf16(acc[mf][nf], al[mf], bh[nf]);
        }
        __syncthreads();
    }

    float* Out = g_Y + ((long long)b * RP + r0 + wm * 32) * CC + c0 + wn * 32;
    const int rr = lane >> 2, cc2 = (lane & 3) * 2;
#pragma unroll
    for (int mf = 0; mf < 2; mf++)
#pragma unroll
        for (int nf = 0; nf < 4; nf++) {
            float* o = Out + (long long)(mf * 16 + rr) * CC + nf * 8 + cc2;
            *(float2*)o = make_float2(acc[mf][nf][0], acc[mf][nf][1]);
            *(float2*)(o + 8LL * CC) = make_float2(acc[mf][nf][2], acc[mf][nf][3]);
        }
}

// ==================== support kernels ====================

// Weff[h][co][c] = sum_d proj_w[co][h*32+d] * v_w[h*32+d][c]
__global__ __launch_bounds__(256)
void weff_kernel(const float* __restrict__ pw, const float* __restrict__ vw) {
    const int h = blockIdx.x, co0 = blockIdx.y * 32, c = threadIdx.x;
    float vv[HD];
#pragma unroll
    for (int d = 0; d < HD; d++) vv[d] = vw[(h * HD + d) * CC + c];
    for (int i = 0; i < 32; i++) {
        const int co = co0 + i;
        float a = 0.f;
#pragma unroll
        for (int d = 0; d < HD; d++) a += pw[co * CC + h * HD + d] * vv[d];
        g_We[(h * CC + co) * CC + c] = a;
    }
}

// Qeff (bf16 hi/lo); pad rows never written (stay zero).
__global__ __launch_bounds__(256)
void qeff_kernel(const float* __restrict__ x_cls, const float* __restrict__ qw,
                 const float* __restrict__ kw, const float* __restrict__ temp) {
    const int b = blockIdx.x, t = threadIdx.x;
    __shared__ float buf[6528];

    for (int i = t; i < CC * VQ; i += 256) buf[i] = x_cls[b * CC * VQ + i];
    __syncthreads();

    float acc[VQ];
#pragma unroll
    for (int v = 0; v < VQ; v++) acc[v] = 0.f;
    const float* wrow = qw + t * CC;
    for (int c2 = 0; c2 < CC; c2++) {
        float w = wrow[c2];
#pragma unroll
        for (int v = 0; v < VQ; v++) acc[v] += w * buf[c2 * VQ + v];
    }
    const float s = temp[t >> 5] * 0.17677669529663687f;
    __syncthreads();
#pragma unroll
    for (int v = 0; v < VQ; v++) buf[v * 260 + t] = acc[v] * s;
    __syncthreads();

    for (int h = 0; h < HH; h++) {
        float kv[HD];
#pragma unroll
        for (int d = 0; d < HD; d++) kv[d] = kw[(h * HD + d) * CC + t];
        for (int v = 0; v < VQ; v++) {
            float a = 0.f;
#pragma unroll
            for (int d = 0; d < HD; d++) a += buf[v * 260 + h * HD + d] * kv[d];
            bf hi, lo; split_bf(a, hi, lo);
            const long long idx = ((long long)b * RP + h * VQ + v) * CC + t;
            g_Qeh[idx] = hi;
            g_Qel[idx] = lo;
        }
    }
}

// Streaming split of x_patch into bf16 hi/lo (natural [b][c][n] layout).
__global__ __launch_bounds__(256)
void convx_kernel(const float* __restrict__ xp) {
    const long long i = ((long long)blockIdx.x * 256 + threadIdx.x) * 4;
    float4 v = *(const float4*)(xp + i);
    bf h0, l0, h1, l1, h2, l2, h3, l3;
    split_bf(v.x, h0, l0); split_bf(v.y, h1, l1);
    split_bf(v.z, h2, l2); split_bf(v.w, h3, l3);
    __nv_bfloat162* ph = (__nv_bfloat162*)(g_Xh + i);
    __nv_bfloat162* pl = (__nv_bfloat162*)(g_Xl + i);
    ph[0] = __nv_bfloat162(h0, h1); ph[1] = __nv_bfloat162(h2, h3);
    pl[0] = __nv_bfloat162(l0, l1); pl[1] = __nv_bfloat162(l2, l3);
}

// Row softmax over g_S rows r<200; emit bf16 hi/lo probabilities.
__global__ __launch_bounds__(256)
void softmax_kernel() {
    const int wid = threadIdx.x >> 5, lane = threadIdx.x & 31;
    const int r = blockIdx.x * 8 + wid, b = blockIdx.y;
    const float* p = g_S + ((long long)b * RP + r) * NTOK;

    float v[50];
    float mx = -1e30f;
#pragma unroll
    for (int i = 0; i < 50; i++) { v[i] = p[i * 32 + lane]; mx = fmaxf(mx, v[i]); }
#pragma unroll
    for (int o = 16; o; o >>= 1) mx = fmaxf(mx, __shfl_xor_sync(0xffffffffu, mx, o));
    float s = 0.f;
#pragma unroll
    for (int i = 0; i < 50; i++) { float e = __expf(v[i] - mx); v[i] = e; s += e; }
#pragma unroll
    for (int o = 16; o; o >>= 1) s += __shfl_xor_sync(0xffffffffu, s, o);
    const float inv = 1.f / s;

    bf* ph = g_Ph + ((long long)b * RP + r) * NTOK;
    bf* pl = g_Pl + ((long long)b * RP + r) * NTOK;
#pragma unroll
    for (int i = 0; i < 50; i++) {
        bf hi, lo; split_bf(v[i] * inv, hi, lo);
        ph[i * 32 + lane] = hi;
        pl[i * 32 + lane] = lo;
    }
}

// Final: out[b][co][v] = proj_b[co] + sum_h sum_c We[h][co][c] * Y[b][h*25+v][c]
__global__ __launch_bounds__(256)
void final_kernel(const float* __restrict__ pb, float* __restrict__ out) {
    const int b = blockIdx.x, gy = blockIdx.y, t = threadIdx.x;
    __shared__ float ys[256 * 27 + 32];

    const int nv = (gy == 0) ? 7 : 6;
    float acc[7];
    const float bias = pb[t];
#pragma unroll
    for (int k = 0; k < 7; k++) acc[k] = bias;

    for (int h = 0; h < HH; h++) {
        __syncthreads();
        for (int i = t; i < VQ * CC; i += 256) {
            int v = i >> 8, c = i & 255;
            ys[c * 27 + v] = g_Y[((long long)b * RP + h * VQ + v) * CC + c];
        }
        __syncthreads();
        const float* we = g_We + (h * CC + t) * CC;
        for (int c = 0; c < CC; c++) {
            float w = we[c];
#pragma unroll
            for (int k = 0; k < 7; k++)
                acc[k] += w * ys[c * 27 + gy + 4 * k];
        }
    }
    for (int k = 0; k < nv; k++)
        out[b * (CC * VQ) + t * VQ + gy + 4 * k] = acc[k];
}

// ---------------------------------------------------------------
extern "C" void kernel_launch(void* const* d_in, const int* in_sizes, int n_in,
                              void* d_out, int out_size) {
    (void)in_sizes; (void)n_in; (void)out_size;
    const float* x_cls   = (const float*)d_in[0];
    const float* x_patch = (const float*)d_in[1];
    const float* q_w     = (const float*)d_in[2];
    const float* k_w     = (const float*)d_in[3];
    const float* v_w     = (const float*)d_in[4];
    const float* temp    = (const float*)d_in[5];
    const float* proj_w  = (const float*)d_in[6];
    const float* proj_b  = (const float*)d_in[7];
    float* out = (float*)d_out;

    const int SMEM1 = 2 * STG1;   // 102400
    const int SMEM2 = 2 * STG2;   // 98304
    cudaFuncSetAttribute(gemm1_mma, cudaFuncAttributeMaxDynamicSharedMemorySize, SMEM1);
    cudaFuncSetAttribute(gemm2_mma, cudaFuncAttributeMaxDynamicSharedMemorySize, SMEM2);

    weff_kernel<<<dim3(HH, 8), 256>>>(proj_w, v_w);
    qeff_kernel<<<BB, 256>>>(x_cls, q_w, k_w, temp);
    convx_kernel<<<(BB * CC * NTOK) / 1024, 256>>>(x_patch);
    gemm1_mma<<<dim3(NTOK / 64, 2, BB), 256, SMEM1>>>();
    softmax_kernel<<<dim3(RR / 8, BB), 256>>>();
    gemm2_mma<<<dim3(4, 2, BB), 256, SMEM2>>>();
    final_kernel<<<dim3(BB, 4), 256>>>(proj_b, out);
}

// round 12
// speedup vs baseline: 1.1005x; 1.0170x over previous
#include <cuda_runtime.h>
#include <cuda_bf16.h>
#include <cstdint>

#define BB   64
#define CC   256
#define NTOK 1600
#define VQ   25
#define HH   8
#define HD   32
#define RR   200
#define RP   256
#define KSPL 5        // gemm2 split-K factor

typedef __nv_bfloat16 bf;

// -------- device scratch (allocation-free rule; zero-init at load) --------
__device__ __align__(16) bf    g_Qeh[BB * RP * CC];   // pad rows 200..255 stay 0
__device__ __align__(16) bf    g_Qel[BB * RP * CC];
__device__ __align__(16) bf    g_Xh [BB * CC * NTOK];
__device__ __align__(16) bf    g_Xl [BB * CC * NTOK];
__device__ __align__(16) bf    g_Ph [BB * RP * NTOK]; // pad rows stay 0
__device__ __align__(16) bf    g_Pl [BB * RP * NTOK];
__device__ __align__(16) float g_S  [BB * RP * NTOK];
__device__ __align__(16) float g_Yp [KSPL * BB * RP * CC];  // split-K partials
__device__ __align__(16) float g_Y  [BB * RP * CC];
__device__ __align__(16) float g_We [HH * CC * CC];

// ==================== PTX helpers (baseline ISA only) ====================
__device__ __forceinline__ uint32_t smem_u32(const void* p) {
    uint32_t a;
    asm("{ .reg .u64 t; cvta.to.shared.u64 t, %1; cvt.u32.u64 %0, t; }" : "=r"(a) : "l"(p));
    return a;
}
__device__ __forceinline__ void ldsm4(uint32_t* r, uint32_t a) {
    asm volatile("ldmatrix.sync.aligned.m8n8.x4.shared.b16 {%0,%1,%2,%3}, [%4];"
                 : "=r"(r[0]), "=r"(r[1]), "=r"(r[2]), "=r"(r[3]) : "r"(a));
}
__device__ __forceinline__ void ldsm4t(uint32_t* r, uint32_t a) {
    asm volatile("ldmatrix.sync.aligned.m8n8.x4.trans.shared.b16 {%0,%1,%2,%3}, [%4];"
                 : "=r"(r[0]), "=r"(r[1]), "=r"(r[2]), "=r"(r[3]) : "r"(a));
}
__device__ __forceinline__ void mma_bf16(float* c, const uint32_t* a, const uint32_t* b) {
    asm volatile("mma.sync.aligned.m16n8k16.row.col.f32.bf16.bf16.f32 "
                 "{%0,%1,%2,%3}, {%4,%5,%6,%7}, {%8,%9}, {%0,%1,%2,%3};"
                 : "+f"(c[0]), "+f"(c[1]), "+f"(c[2]), "+f"(c[3])
                 : "r"(a[0]), "r"(a[1]), "r"(a[2]), "r"(a[3]), "r"(b[0]), "r"(b[1]));
}
__device__ __forceinline__ void cp16(uint32_t d, const void* g) {
    asm volatile("cp.async.cg.shared.global [%0], [%1], 16;" :: "r"(d), "l"(g) : "memory");
}
#define CP_COMMIT() asm volatile("cp.async.commit_group;" ::: "memory")
#define CP_WAIT(n)  asm volatile("cp.async.wait_group %0;" :: "n"(n) : "memory")

__device__ __forceinline__ void split_bf(float v, bf& h, bf& l) {
    h = __float2bfloat16(v);
    l = __float2bfloat16(v - __bfloat162float(h));
}

// ==================== GEMM1: S[b][r][n] = Qe @ X (contract c=256) ====================
// Block 128(r) x 64(n); warps 4(m) x 2(n) -> warp tile 32 x 32. 2 CTAs/SM.
#define B1P  144                       // padded B row bytes: 64*2 + 16
#define STG1 (32768 + 2 * 64 * B1P)    // 51200
__global__ __launch_bounds__(256, 2)
void gemm1_mma() {
    extern __shared__ char smem[];
    constexpr int A_HI = 0, A_LO = 16384, B_HI = 32768, B_LO = 32768 + 64 * B1P;
    const int b = blockIdx.z, r0 = blockIdx.y * 128, n0 = blockIdx.x * 64;
    const int tid = threadIdx.x, lane = tid & 31, wid = tid >> 5;
    const int wm = wid >> 1, wn = wid & 1;
    const uint32_t sb = smem_u32(smem);

    float acc[2][4][4];
#pragma unroll
    for (int i = 0; i < 2; i++)
#pragma unroll
        for (int j = 0; j < 4; j++)
#pragma unroll
            for (int k = 0; k < 4; k++) acc[i][j][k] = 0.f;

    const bf* Ah = g_Qeh + ((long long)b * RP + r0) * CC;
    const bf* Al = g_Qel + ((long long)b * RP + r0) * CC;
    const bf* Bh = g_Xh + (long long)b * CC * NTOK + n0;
    const bf* Bl = g_Xl + (long long)b * CC * NTOK + n0;

    auto load = [&](int kc, int st) {
        const uint32_t base = sb + st * STG1;
#pragma unroll
        for (int it = 0; it < 4; it++) {
            int idx = tid + it * 256;
            int r = idx >> 3, c = idx & 7;
            uint32_t off = (uint32_t)(r * 128 + c * 16);
            off ^= (off >> 3) & 0x70;
            const long long go = (long long)r * CC + kc * 64 + c * 8;
            cp16(base + A_HI + off, Ah + go);
            cp16(base + A_LO + off, Al + go);
        }
#pragma unroll
        for (int it = 0; it < 2; it++) {
            int idx = tid + it * 256;
            int r = idx >> 3, c8 = idx & 7;
            const long long go = (long long)(kc * 64 + r) * NTOK + c8 * 8;
            cp16(base + B_HI + r * B1P + c8 * 16, Bh + go);
            cp16(base + B_LO + r * B1P + c8 * 16, Bl + go);
        }
    };

    load(0, 0);
    CP_COMMIT();

    for (int kc = 0; kc < 4; kc++) {
        if (kc + 1 < 4) {
            load(kc + 1, (kc + 1) & 1);
            CP_COMMIT();
            CP_WAIT(1);
        } else {
            CP_WAIT(0);
        }
        __syncthreads();

        const uint32_t base = sb + (kc & 1) * STG1;
#pragma unroll
        for (int ks = 0; ks < 4; ks++) {
            uint32_t ah[2][4], al[2][4], bh[4][2], bl[4][2];
            const uint32_t kbyte = ks * 32 + (lane >> 4) * 16;
#pragma unroll
            for (int mf = 0; mf < 2; mf++) {
                uint32_t row = wm * 32 + mf * 16 + (lane & 15);
                uint32_t off = row * 128 + kbyte;
                off ^= (off >> 3) & 0x70;
                ldsm4(ah[mf], base + A_HI + off);
                ldsm4(al[mf], base + A_LO + off);
            }
            // B: one ldsm4t per nf-pair. m0/m1 = k0-7/k8-15 for n-cols [0,8),
            // m2/m3 = same k for n-cols [8,16).
#pragma unroll
            for (int nf2 = 0; nf2 < 2; nf2++) {
                uint32_t off = (ks * 16 + (lane & 15)) * B1P
                             + (wn * 32 + nf2 * 16) * 2 + (lane >> 4) * 16;
                uint32_t t[4];
                ldsm4t(t, base + B_HI + off);
                bh[2 * nf2][0] = t[0]; bh[2 * nf2][1] = t[1];
                bh[2 * nf2 + 1][0] = t[2]; bh[2 * nf2 + 1][1] = t[3];
                ldsm4t(t, base + B_LO + off);
                bl[2 * nf2][0] = t[0]; bl[2 * nf2][1] = t[1];
                bl[2 * nf2 + 1][0] = t[2]; bl[2 * nf2 + 1][1] = t[3];
            }
            // term-major: consecutive MMAs hit different accumulators
#pragma unroll
            for (int mf = 0; mf < 2; mf++)
#pragma unroll
                for (int nf = 0; nf < 4; nf++) mma_bf16(acc[mf][nf], ah[mf], bh[nf]);
#pragma unroll
            for (int mf = 0; mf < 2; mf++)
#pragma unroll
                for (int nf = 0; nf < 4; nf++) mma_bf16(acc[mf][nf], ah[mf], bl[nf]);
#pragma unroll
            for (int mf = 0; mf < 2; mf++)
#pragma unroll
                for (int nf = 0; nf < 4; nf++) mma_bf16(acc[mf][nf], al[mf], bh[nf]);
        }
        __syncthreads();
    }

    float* Out = g_S + ((long long)b * RP + r0 + wm * 32) * NTOK + n0 + wn * 32;
    const int rr = lane >> 2, cc2 = (lane & 3) * 2;
#pragma unroll
    for (int mf = 0; mf < 2; mf++)
#pragma unroll
        for (int nf = 0; nf < 4; nf++) {
            float* o = Out + (long long)(mf * 16 + rr) * NTOK + nf * 8 + cc2;
            *(float2*)o = make_float2(acc[mf][nf][0], acc[mf][nf][1]);
            *(float2*)(o + 8LL * NTOK) = make_float2(acc[mf][nf][2], acc[mf][nf][3]);
        }
}

// ==================== GEMM2: Yp[p][b][r][c] = P @ X^T over k-slice p ====================
// Block 128(r) x 64(c); warps 4(m) x 2(n). Split-K x5: blockIdx.y = p*2 + (r0/128).
#define STG2 49152
__global__ __launch_bounds__(256, 2)
void gemm2_mma() {
    extern __shared__ char smem[];
    constexpr int A_HI = 0, A_LO = 16384, B_HI = 32768, B_LO = 40960;
    const int b = blockIdx.z, c0 = blockIdx.x * 64;
    const int p = blockIdx.y >> 1, r0 = (blockIdx.y & 1) * 128;
    const int tid = threadIdx.x, lane = tid & 31, wid = tid >> 5;
    const int wm = wid >> 1, wn = wid & 1;
    const uint32_t sb = smem_u32(smem);

    float acc[2][4][4];
#pragma unroll
    for (int i = 0; i < 2; i++)
#pragma unroll
        for (int j = 0; j < 4; j++)
#pragma unroll
            for (int k = 0; k < 4; k++) acc[i][j][k] = 0.f;

    const bf* Ah = g_Ph + ((long long)b * RP + r0) * NTOK;
    const bf* Al = g_Pl + ((long long)b * RP + r0) * NTOK;
    const bf* Bh = g_Xh + ((long long)b * CC + c0) * NTOK;
    const bf* Bl = g_Xl + ((long long)b * CC + c0) * NTOK;

    auto load = [&](int kc, int st) {
        const uint32_t base = sb + st * STG2;
#pragma unroll
        for (int it = 0; it < 4; it++) {
            int idx = tid + it * 256;
            int r = idx >> 3, c = idx & 7;
            uint32_t off = (uint32_t)(r * 128 + c * 16);
            off ^= (off >> 3) & 0x70;
            const long long ga = (long long)r * NTOK + kc * 64 + c * 8;
            cp16(base + A_HI + off, Ah + ga);
            cp16(base + A_LO + off, Al + ga);
        }
#pragma unroll
        for (int it = 0; it < 2; it++) {
            int idx = tid + it * 256;
            int r = idx >> 3, c = idx & 7;
            uint32_t off = (uint32_t)(r * 128 + c * 16);
            off ^= (off >> 3) & 0x70;
            const long long gb = (long long)r * NTOK + kc * 64 + c * 8;
            cp16(base + B_HI + off, Bh + gb);
            cp16(base + B_LO + off, Bl + gb);
        }
    };

    load(p * KSPL, 0);
    CP_COMMIT();

    for (int j = 0; j < KSPL; j++) {
        if (j + 1 < KSPL) {
            load(p * KSPL + j + 1, (j + 1) & 1);
            CP_COMMIT();
            CP_WAIT(1);
        } else {
            CP_WAIT(0);
        }
        __syncthreads();

        const uint32_t base = sb + (j & 1) * STG2;
#pragma unroll
        for (int ks = 0; ks < 4; ks++) {
            uint32_t ah[2][4], al[2][4], bh[4][2], bl[4][2];
            const uint32_t kbyte = ks * 32 + (lane >> 4) * 16;
#pragma unroll
            for (int mf = 0; mf < 2; mf++) {
                uint32_t row = wm * 32 + mf * 16 + (lane & 15);
                uint32_t off = row * 128 + kbyte;
                off ^= (off >> 3) & 0x70;
                ldsm4(ah[mf], base + A_HI + off);
                ldsm4(al[mf], base + A_LO + off);
            }
            // B non-trans: one ldsm4 per nf-pair.
            // m0: rows nf2*16+0..7 k0-7 | m1: same rows k8-15 | m2/m3: rows+8.
#pragma unroll
            for (int nf2 = 0; nf2 < 2; nf2++) {
                uint32_t row = wn * 32 + nf2 * 16 + (lane >> 4) * 8 + (lane & 7);
                uint32_t kb = ks * 32 + ((lane >> 3) & 1) * 16;
                uint32_t off = row * 128 + kb;
                off ^= (off >> 3) & 0x70;
                uint32_t t[4];
                ldsm4(t, base + B_HI + off);
                bh[2 * nf2][0] = t[0]; bh[2 * nf2][1] = t[1];
                bh[2 * nf2 + 1][0] = t[2]; bh[2 * nf2 + 1][1] = t[3];
                ldsm4(t, base + B_LO + off);
                bl[2 * nf2][0] = t[0]; bl[2 * nf2][1] = t[1];
                bl[2 * nf2 + 1][0] = t[2]; bl[2 * nf2 + 1][1] = t[3];
            }
            // term-major MMA issue
#pragma unroll
            for (int mf = 0; mf < 2; mf++)
#pragma unroll
                for (int nf = 0; nf < 4; nf++) mma_bf16(acc[mf][nf], ah[mf], bh[nf]);
#pragma unroll
            for (int mf = 0; mf < 2; mf++)
#pragma unroll
                for (int nf = 0; nf < 4; nf++) mma_bf16(acc[mf][nf], ah[mf], bl[nf]);
#pragma unroll
            for (int mf = 0; mf < 2; mf++)
#pragma unroll
                for (int nf = 0; nf < 4; nf++) mma_bf16(acc[mf][nf], al[mf], bh[nf]);
        }
        __syncthreads();
    }

    float* Out = g_Yp + (long long)p * (BB * RP * CC)
               + ((long long)b * RP + r0 + wm * 32) * CC + c0 + wn * 32;
    const int rr = lane >> 2, cc2 = (lane & 3) * 2;
#pragma unroll
    for (int mf = 0; mf < 2; mf++)
#pragma unroll
        for (int nf = 0; nf < 4; nf++) {
            float* o = Out + (long long)(mf * 16 + rr) * CC + nf * 8 + cc2;
            *(float2*)o = make_float2(acc[mf][nf][0], acc[mf][nf][1]);
            *(float2*)(o + 8LL * CC) = make_float2(acc[mf][nf][2], acc[mf][nf][3]);
        }
}

// Reduce split-K partials: g_Y = sum_p g_Yp[p]
__global__ __launch_bounds__(256)
void reduce_y() {
    const long long i = ((long long)blockIdx.x * 256 + threadIdx.x) * 4;
    float4 s = *(const float4*)(g_Yp + i);
#pragma unroll
    for (int p = 1; p < KSPL; p++) {
        float4 v = *(const float4*)(g_Yp + (long long)p * (BB * RP * CC) + i);
        s.x += v.x; s.y += v.y; s.z += v.z; s.w += v.w;
    }
    *(float4*)(g_Y + i) = s;
}

// ==================== support kernels ====================

// Weff[h][co][c] = sum_d proj_w[co][h*32+d] * v_w[h*32+d][c]
__global__ __launch_bounds__(256)
void weff_kernel(const float* __restrict__ pw, const float* __restrict__ vw) {
    const int h = blockIdx.x, co0 = blockIdx.y * 32, c = threadIdx.x;
    float vv[HD];
#pragma unroll
    for (int d = 0; d < HD; d++) vv[d] = vw[(h * HD + d) * CC + c];
    for (int i = 0; i < 32; i++) {
        const int co = co0 + i;
        float a = 0.f;
#pragma unroll
        for (int d = 0; d < HD; d++) a += pw[co * CC + h * HD + d] * vv[d];
        g_We[(h * CC + co) * CC + c] = a;
    }
}

// Qeff (bf16 hi/lo); pad rows never written (stay zero).
__global__ __launch_bounds__(256)
void qeff_kernel(const float* __restrict__ x_cls, const float* __restrict__ qw,
                 const float* __restrict__ kw, const float* __restrict__ temp) {
    const int b = blockIdx.x, t = threadIdx.x;
    __shared__ float buf[6528];

    for (int i = t; i < CC * VQ; i += 256) buf[i] = x_cls[b * CC * VQ + i];
    __syncthreads();

    float acc[VQ];
#pragma unroll
    for (int v = 0; v < VQ; v++) acc[v] = 0.f;
    const float* wrow = qw + t * CC;
    for (int c2 = 0; c2 < CC; c2++) {
        float w = wrow[c2];
#pragma unroll
        for (int v = 0; v < VQ; v++) acc[v] += w * buf[c2 * VQ + v];
    }
    const float s = temp[t >> 5] * 0.17677669529663687f;
    __syncthreads();
#pragma unroll
    for (int v = 0; v < VQ; v++) buf[v * 260 + t] = acc[v] * s;
    __syncthreads();

    for (int h = 0; h < HH; h++) {
        float kv[HD];
#pragma unroll
        for (int d = 0; d < HD; d++) kv[d] = kw[(h * HD + d) * CC + t];
        for (int v = 0; v < VQ; v++) {
            float a = 0.f;
#pragma unroll
            for (int d = 0; d < HD; d++) a += buf[v * 260 + h * HD + d] * kv[d];
            bf hi, lo; split_bf(a, hi, lo);
            const long long idx = ((long long)b * RP + h * VQ + v) * CC + t;
            g_Qeh[idx] = hi;
            g_Qel[idx] = lo;
        }
    }
}

// Streaming split of x_patch into bf16 hi/lo (natural [b][c][n] layout).
__global__ __launch_bounds__(256)
void convx_kernel(const float* __restrict__ xp) {
    const long long i = ((long long)blockIdx.x * 256 + threadIdx.x) * 4;
    float4 v = *(const float4*)(xp + i);
    bf h0, l0, h1, l1, h2, l2, h3, l3;
    split_bf(v.x, h0, l0); split_bf(v.y, h1, l1);
    split_bf(v.z, h2, l2); split_bf(v.w, h3, l3);
    __nv_bfloat162* ph = (__nv_bfloat162*)(g_Xh + i);
    __nv_bfloat162* pl = (__nv_bfloat162*)(g_Xl + i);
    ph[0] = __nv_bfloat162(h0, h1); ph[1] = __nv_bfloat162(h2, h3);
    pl[0] = __nv_bfloat162(l0, l1); pl[1] = __nv_bfloat162(l2, l3);
}

// Row softmax over g_S rows r<200; emit bf16 hi/lo probabilities.
__global__ __launch_bounds__(256)
void softmax_kernel() {
    const int wid = threadIdx.x >> 5, lane = threadIdx.x & 31;
    const int r = blockIdx.x * 8 + wid, b = blockIdx.y;
    const float* p = g_S + ((long long)b * RP + r) * NTOK;

    float v[50];
    float mx = -1e30f;
#pragma unroll
    for (int i = 0; i < 50; i++) { v[i] = p[i * 32 + lane]; mx = fmaxf(mx, v[i]); }
#pragma unroll
    for (int o = 16; o; o >>= 1) mx = fmaxf(mx, __shfl_xor_sync(0xffffffffu, mx, o));
    float s = 0.f;
#pragma unroll
    for (int i = 0; i < 50; i++) { float e = __expf(v[i] - mx); v[i] = e; s += e; }
#pragma unroll
    for (int o = 16; o; o >>= 1) s += __shfl_xor_sync(0xffffffffu, s, o);
    const float inv = 1.f / s;

    bf* ph = g_Ph + ((long long)b * RP + r) * NTOK;
    bf* pl = g_Pl + ((long long)b * RP + r) * NTOK;
#pragma unroll
    for (int i = 0; i < 50; i++) {
        bf hi, lo; split_bf(v[i] * inv, hi, lo);
        ph[i * 32 + lane] = hi;
        pl[i * 32 + lane] = lo;
    }
}

// Final: out[b][co][v] = proj_b[co] + sum_h sum_c We[h][co][c] * Y[b][h*25+v][c]
__global__ __launch_bounds__(256)
void final_kernel(const float* __restrict__ pb, float* __restrict__ out) {
    const int b = blockIdx.x, gy = blockIdx.y, t = threadIdx.x;
    __shared__ float ys[256 * 27 + 32];

    const int nv = (gy == 0) ? 7 : 6;
    float acc[7];
    const float bias = pb[t];
#pragma unroll
    for (int k = 0; k < 7; k++) acc[k] = bias;

    for (int h = 0; h < HH; h++) {
        __syncthreads();
        for (int i = t; i < VQ * CC; i += 256) {
            int v = i >> 8, c = i & 255;
            ys[c * 27 + v] = g_Y[((long long)b * RP + h * VQ + v) * CC + c];
        }
        __syncthreads();
        const float* we = g_We + (h * CC + t) * CC;
        for (int c = 0; c < CC; c++) {
            float w = we[c];
#pragma unroll
            for (int k = 0; k < 7; k++)
                acc[k] += w * ys[c * 27 + gy + 4 * k];
        }
    }
    for (int k = 0; k < nv; k++)
        out[b * (CC * VQ) + t * VQ + gy + 4 * k] = acc[k];
}

// ---------------------------------------------------------------
extern "C" void kernel_launch(void* const* d_in, const int* in_sizes, int n_in,
                              void* d_out, int out_size) {
    (void)in_sizes; (void)n_in; (void)out_size;
    const float* x_cls   = (const float*)d_in[0];
    const float* x_patch = (const float*)d_in[1];
    const float* q_w     = (const float*)d_in[2];
    const float* k_w     = (const float*)d_in[3];
    const float* v_w     = (const float*)d_in[4];
    const float* temp    = (const float*)d_in[5];
    const float* proj_w  = (const float*)d_in[6];
    const float* proj_b  = (const float*)d_in[7];
    float* out = (float*)d_out;

    const int SMEM1 = 2 * STG1;   // 102400
    const int SMEM2 = 2 * STG2;   // 98304
    cudaFuncSetAttribute(gemm1_mma, cudaFuncAttributeMaxDynamicSharedMemorySize, SMEM1);
    cudaFuncSetAttribute(gemm2_mma, cudaFuncAttributeMaxDynamicSharedMemorySize, SMEM2);

    weff_kernel<<<dim3(HH, 8), 256>>>(proj_w, v_w);
    qeff_kernel<<<BB, 256>>>(x_cls, q_w, k_w, temp);
    convx_kernel<<<(BB * CC * NTOK) / 1024, 256>>>(x_patch);
    gemm1_mma<<<dim3(NTOK / 64, 2, BB), 256, SMEM1>>>();
    softmax_kernel<<<dim3(RR / 8, BB), 256>>>();
    gemm2_mma<<<dim3(4, 2 * KSPL, BB), 256, SMEM2>>>();
    reduce_y<<<(BB * RP * CC) / 1024, 256>>>();
    final_kernel<<<dim3(BB, 4), 256>>>(proj_b, out);
}

// round 15
// speedup vs baseline: 1.8837x; 1.7117x over previous
#include <cuda_runtime.h>
#include <cuda_bf16.h>
#include <cstdint>

#define BB   64
#define CC   256
#define NTOK 1600
#define VQ   25
#define HH   8
#define HD   32
#define RR   200
#define RP   256
#define KSPL 5        // gemm2 split-K factor
#define K2   2048     // final_mma K = HH*CC

typedef __nv_bfloat16 bf;

// -------- device scratch (allocation-free rule; zero-init at load) --------
__device__ __align__(16) bf    g_Qeh[BB * RP * CC];   // pad rows 200..255 stay 0
__device__ __align__(16) bf    g_Qel[BB * RP * CC];
__device__ __align__(16) bf    g_Xh [BB * CC * NTOK];
__device__ __align__(16) bf    g_Xl [BB * CC * NTOK];
__device__ __align__(16) bf    g_Ph [BB * RP * NTOK]; // pad rows stay 0
__device__ __align__(16) bf    g_Pl [BB * RP * NTOK];
__device__ __align__(16) float g_S  [BB * RP * NTOK];
__device__ __align__(16) float g_Yp [KSPL * BB * RP * CC];  // split-K partials
__device__ __align__(16) bf    g_Y2h[BB * 32 * K2];   // Y transposed: [b][v(pad32)][h*256+c]; pad v rows stay 0
__device__ __align__(16) bf    g_Y2l[BB * 32 * K2];
__device__ __align__(16) bf    g_We2h[CC * K2];       // folded proj@v weights: [co][h*256+c]
__device__ __align__(16) bf    g_We2l[CC * K2];

// ==================== PTX helpers (baseline ISA only) ====================
__device__ __forceinline__ uint32_t smem_u32(const void* p) {
    uint32_t a;
    asm("{ .reg .u64 t; cvta.to.shared.u64 t, %1; cvt.u32.u64 %0, t; }" : "=r"(a) : "l"(p));
    return a;
}
__device__ __forceinline__ void ldsm4(uint32_t* r, uint32_t a) {
    asm volatile("ldmatrix.sync.aligned.m8n8.x4.shared.b16 {%0,%1,%2,%3}, [%4];"
                 : "=r"(r[0]), "=r"(r[1]), "=r"(r[2]), "=r"(r[3]) : "r"(a));
}
__device__ __forceinline__ void ldsm4t(uint32_t* r, uint32_t a) {
    asm volatile("ldmatrix.sync.aligned.m8n8.x4.trans.shared.b16 {%0,%1,%2,%3}, [%4];"
                 : "=r"(r[0]), "=r"(r[1]), "=r"(r[2]), "=r"(r[3]) : "r"(a));
}
__device__ __forceinline__ void mma_bf16(float* c, const uint32_t* a, const uint32_t* b) {
    asm volatile("mma.sync.aligned.m16n8k16.row.col.f32.bf16.bf16.f32 "
                 "{%0,%1,%2,%3}, {%4,%5,%6,%7}, {%8,%9}, {%0,%1,%2,%3};"
                 : "+f"(c[0]), "+f"(c[1]), "+f"(c[2]), "+f"(c[3])
                 : "r"(a[0]), "r"(a[1]), "r"(a[2]), "r"(a[3]), "r"(b[0]), "r"(b[1]));
}
__device__ __forceinline__ void cp16(uint32_t d, const void* g) {
    asm volatile("cp.async.cg.shared.global [%0], [%1], 16;" :: "r"(d), "l"(g) : "memory");
}
#define CP_COMMIT() asm volatile("cp.async.commit_group;" ::: "memory")
#define CP_WAIT(n)  asm volatile("cp.async.wait_group %0;" :: "n"(n) : "memory")

__device__ __forceinline__ void split_bf(float v, bf& h, bf& l) {
    h = __float2bfloat16(v);
    l = __float2bfloat16(v - __bfloat162float(h));
}

// ==================== GEMM1: S[b][r][n] = Qe @ X (contract c=256) ====================
// Block 128(r) x 64(n); warps 4(m) x 2(n) -> warp tile 32 x 32. 2 CTAs/SM.
#define B1P  144                       // padded B row bytes: 64*2 + 16
#define STG1 (32768 + 2 * 64 * B1P)    // 51200
__global__ __launch_bounds__(256, 2)
void gemm1_mma() {
    extern __shared__ char smem[];
    constexpr int A_HI = 0, A_LO = 16384, B_HI = 32768, B_LO = 32768 + 64 * B1P;
    const int b = blockIdx.z, r0 = blockIdx.y * 128, n0 = blockIdx.x * 64;
    const int tid = threadIdx.x, lane = tid & 31, wid = tid >> 5;
    const int wm = wid >> 1, wn = wid & 1;
    const uint32_t sb = smem_u32(smem);

    float acc[2][4][4];
#pragma unroll
    for (int i = 0; i < 2; i++)
#pragma unroll
        for (int j = 0; j < 4; j++)
#pragma unroll
            for (int k = 0; k < 4; k++) acc[i][j][k] = 0.f;

    const bf* Ah = g_Qeh + ((long long)b * RP + r0) * CC;
    const bf* Al = g_Qel + ((long long)b * RP + r0) * CC;
    const bf* Bh = g_Xh + (long long)b * CC * NTOK + n0;
    const bf* Bl = g_Xl + (long long)b * CC * NTOK + n0;

    auto load = [&](int kc, int st) {
        const uint32_t base = sb + st * STG1;
#pragma unroll
        for (int it = 0; it < 4; it++) {
            int idx = tid + it * 256;
            int r = idx >> 3, c = idx & 7;
            uint32_t off = (uint32_t)(r * 128 + c * 16);
            off ^= (off >> 3) & 0x70;
            const long long go = (long long)r * CC + kc * 64 + c * 8;
            cp16(base + A_HI + off, Ah + go);
            cp16(base + A_LO + off, Al + go);
        }
#pragma unroll
        for (int it = 0; it < 2; it++) {
            int idx = tid + it * 256;
            int r = idx >> 3, c8 = idx & 7;
            const long long go = (long long)(kc * 64 + r) * NTOK + c8 * 8;
            cp16(base + B_HI + r * B1P + c8 * 16, Bh + go);
            cp16(base + B_LO + r * B1P + c8 * 16, Bl + go);
        }
    };

    load(0, 0);
    CP_COMMIT();

    for (int kc = 0; kc < 4; kc++) {
        if (kc + 1 < 4) {
            load(kc + 1, (kc + 1) & 1);
            CP_COMMIT();
            CP_WAIT(1);
        } else {
            CP_WAIT(0);
        }
        __syncthreads();

        const uint32_t base = sb + (kc & 1) * STG1;
#pragma unroll
        for (int ks = 0; ks < 4; ks++) {
            uint32_t ah[2][4], al[2][4], bh[4][2], bl[4][2];
            const uint32_t kbyte = ks * 32 + (lane >> 4) * 16;
#pragma unroll
            for (int mf = 0; mf < 2; mf++) {
                uint32_t row = wm * 32 + mf * 16 + (lane & 15);
                uint32_t off = row * 128 + kbyte;
                off ^= (off >> 3) & 0x70;
                ldsm4(ah[mf], base + A_HI + off);
                ldsm4(al[mf], base + A_LO + off);
            }
#pragma unroll
            for (int nf2 = 0; nf2 < 2; nf2++) {
                uint32_t off = (ks * 16 + (lane & 15)) * B1P
                             + (wn * 32 + nf2 * 16) * 2 + (lane >> 4) * 16;
                uint32_t t[4];
                ldsm4t(t, base + B_HI + off);
                bh[2 * nf2][0] = t[0]; bh[2 * nf2][1] = t[1];
                bh[2 * nf2 + 1][0] = t[2]; bh[2 * nf2 + 1][1] = t[3];
                ldsm4t(t, base + B_LO + off);
                bl[2 * nf2][0] = t[0]; bl[2 * nf2][1] = t[1];
                bl[2 * nf2 + 1][0] = t[2]; bl[2 * nf2 + 1][1] = t[3];
            }
#pragma unroll
            for (int mf = 0; mf < 2; mf++)
#pragma unroll
                for (int nf = 0; nf < 4; nf++) mma_bf16(acc[mf][nf], ah[mf], bh[nf]);
#pragma unroll
            for (int mf = 0; mf < 2; mf++)
#pragma unroll
                for (int nf = 0; nf < 4; nf++) mma_bf16(acc[mf][nf], ah[mf], bl[nf]);
#pragma unroll
            for (int mf = 0; mf < 2; mf++)
#pragma unroll
                for (int nf = 0; nf < 4; nf++) mma_bf16(acc[mf][nf], al[mf], bh[nf]);
        }
        __syncthreads();
    }

    float* Out = g_S + ((long long)b * RP + r0 + wm * 32) * NTOK + n0 + wn * 32;
    const int rr = lane >> 2, cc2 = (lane & 3) * 2;
#pragma unroll
    for (int mf = 0; mf < 2; mf++)
#pragma unroll
        for (int nf = 0; nf < 4; nf++) {
            float* o = Out + (long long)(mf * 16 + rr) * NTOK + nf * 8 + cc2;
            *(float2*)o = make_float2(acc[mf][nf][0], acc[mf][nf][1]);
            *(float2*)(o + 8LL * NTOK) = make_float2(acc[mf][nf][2], acc[mf][nf][3]);
        }
}

// ==================== GEMM2: Yp[p][b][r][c] = P @ X^T over k-slice p ====================
#define STG2 49152
__global__ __launch_bounds__(256, 2)
void gemm2_mma() {
    extern __shared__ char smem[];
    constexpr int A_HI = 0, A_LO = 16384, B_HI = 32768, B_LO = 40960;
    const int b = blockIdx.z, c0 = blockIdx.x * 64;
    const int p = blockIdx.y >> 1, r0 = (blockIdx.y & 1) * 128;
    const int tid = threadIdx.x, lane = tid & 31, wid = tid >> 5;
    const int wm = wid >> 1, wn = wid & 1;
    const uint32_t sb = smem_u32(smem);

    float acc[2][4][4];
#pragma unroll
    for (int i = 0; i < 2; i++)
#pragma unroll
        for (int j = 0; j < 4; j++)
#pragma unroll
            for (int k = 0; k < 4; k++) acc[i][j][k] = 0.f;

    const bf* Ah = g_Ph + ((long long)b * RP + r0) * NTOK;
    const bf* Al = g_Pl + ((long long)b * RP + r0) * NTOK;
    const bf* Bh = g_Xh + ((long long)b * CC + c0) * NTOK;
    const bf* Bl = g_Xl + ((long long)b * CC + c0) * NTOK;

    auto load = [&](int kc, int st) {
        const uint32_t base = sb + st * STG2;
#pragma unroll
        for (int it = 0; it < 4; it++) {
            int idx = tid + it * 256;
            int r = idx >> 3, c = idx & 7;
            uint32_t off = (uint32_t)(r * 128 + c * 16);
            off ^= (off >> 3) & 0x70;
            const long long ga = (long long)r * NTOK + kc * 64 + c * 8;
            cp16(base + A_HI + off, Ah + ga);
            cp16(base + A_LO + off, Al + ga);
        }
#pragma unroll
        for (int it = 0; it < 2; it++) {
            int idx = tid + it * 256;
            int r = idx >> 3, c = idx & 7;
            uint32_t off = (uint32_t)(r * 128 + c * 16);
            off ^= (off >> 3) & 0x70;
            const long long gb = (long long)r * NTOK + kc * 64 + c * 8;
            cp16(base + B_HI + off, Bh + gb);
            cp16(base + B_LO + off, Bl + gb);
        }
    };

    load(p * KSPL, 0);
    CP_COMMIT();

    for (int j = 0; j < KSPL; j++) {
        if (j + 1 < KSPL) {
            load(p * KSPL + j + 1, (j + 1) & 1);
            CP_COMMIT();
            CP_WAIT(1);
        } else {
            CP_WAIT(0);
        }
        __syncthreads();

        const uint32_t base = sb + (j & 1) * STG2;
#pragma unroll
        for (int ks = 0; ks < 4; ks++) {
            uint32_t ah[2][4], al[2][4], bh[4][2], bl[4][2];
            const uint32_t kbyte = ks * 32 + (lane >> 4) * 16;
#pragma unroll
            for (int mf = 0; mf < 2; mf++) {
                uint32_t row = wm * 32 + mf * 16 + (lane & 15);
                uint32_t off = row * 128 + kbyte;
                off ^= (off >> 3) & 0x70;
                ldsm4(ah[mf], base + A_HI + off);
                ldsm4(al[mf], base + A_LO + off);
            }
#pragma unroll
            for (int nf2 = 0; nf2 < 2; nf2++) {
                uint32_t row = wn * 32 + nf2 * 16 + (lane >> 4) * 8 + (lane & 7);
                uint32_t kb = ks * 32 + ((lane >> 3) & 1) * 16;
                uint32_t off = row * 128 + kb;
                off ^= (off >> 3) & 0x70;
                uint32_t t[4];
                ldsm4(t, base + B_HI + off);
                bh[2 * nf2][0] = t[0]; bh[2 * nf2][1] = t[1];
                bh[2 * nf2 + 1][0] = t[2]; bh[2 * nf2 + 1][1] = t[3];
                ldsm4(t, base + B_LO + off);
                bl[2 * nf2][0] = t[0]; bl[2 * nf2][1] = t[1];
                bl[2 * nf2 + 1][0] = t[2]; bl[2 * nf2 + 1][1] = t[3];
            }
#pragma unroll
            for (int mf = 0; mf < 2; mf++)
#pragma unroll
                for (int nf = 0; nf < 4; nf++) mma_bf16(acc[mf][nf], ah[mf], bh[nf]);
#pragma unroll
            for (int mf = 0; mf < 2; mf++)
#pragma unroll
                for (int nf = 0; nf < 4; nf++) mma_bf16(acc[mf][nf], ah[mf], bl[nf]);
#pragma unroll
            for (int mf = 0; mf < 2; mf++)
#pragma unroll
                for (int nf = 0; nf < 4; nf++) mma_bf16(acc[mf][nf], al[mf], bh[nf]);
        }
        __syncthreads();
    }

    float* Out = g_Yp + (long long)p * (BB * RP * CC)
               + ((long long)b * RP + r0 + wm * 32) * CC + c0 + wn * 32;
    const int rr = lane >> 2, cc2 = (lane & 3) * 2;
#pragma unroll
    for (int mf = 0; mf < 2; mf++)
#pragma unroll
        for (int nf = 0; nf < 4; nf++) {
            float* o = Out + (long long)(mf * 16 + rr) * CC + nf * 8 + cc2;
            *(float2*)o = make_float2(acc[mf][nf][0], acc[mf][nf][1]);
            *(float2*)(o + 8LL * CC) = make_float2(acc[mf][nf][2], acc[mf][nf][3]);
        }
}

// ==================== reduce_yt: sum split-K partials -> transposed bf16 Y2 ==========
// Y2[b][v][h*256+c] = sum_p Yp[p][b][h*25+v][c], split hi/lo. Pad v rows stay 0.
__global__ __launch_bounds__(256)
void reduce_yt() {
    const int hv = blockIdx.x, b = blockIdx.y, c = threadIdx.x;
    const int h = hv / VQ, v = hv % VQ;
    const long long src = ((long long)b * RP + hv) * CC + c;
    float s = g_Yp[src];
#pragma unroll
    for (int p = 1; p < KSPL; p++) s += g_Yp[(long long)p * (BB * RP * CC) + src];
    bf hi, lo; split_bf(s, hi, lo);
    const long long dst = ((long long)b * 32 + v) * K2 + h * CC + c;
    g_Y2h[dst] = hi;
    g_Y2l[dst] = lo;
}

// ==================== final_mma: out[b] = We2 @ Y2[b]^T + bias ====================
// M=256 (2 blocks of 128), N=32 (v, 25 real), K=2048. Warps 4(m) x 2(n), warp 32x16.
#define STGF 40960    // A hi/lo 16KB each + B hi/lo 4KB each
__global__ __launch_bounds__(256, 2)
void final_mma(const float* __restrict__ pb, float* __restrict__ out) {
    extern __shared__ char smem[];
    constexpr int A_HI = 0, A_LO = 16384, B_HI = 32768, B_LO = 36864;
    const int b = blockIdx.z, co0 = blockIdx.x * 128;
    const int tid = threadIdx.x, lane = tid & 31, wid = tid >> 5;
    const int wm = wid >> 1, wn = wid & 1;
    const uint32_t sb = smem_u32(smem);

    float acc[2][2][4];
#pragma unroll
    for (int i = 0; i < 2; i++)
#pragma unroll
        for (int j = 0; j < 2; j++)
#pragma unroll
            for (int k = 0; k < 4; k++) acc[i][j][k] = 0.f;

    const bf* Ah = g_We2h + (long long)co0 * K2;
    const bf* Al = g_We2l + (long long)co0 * K2;
    const bf* Bh = g_Y2h + (long long)b * 32 * K2;
    const bf* Bl = g_Y2l + (long long)b * 32 * K2;

    auto load = [&](int kc, int st) {
        const uint32_t base = sb + st * STGF;
#pragma unroll
        for (int it = 0; it < 4; it++) {
            int idx = tid + it * 256;
            int r = idx >> 3, c = idx & 7;
            uint32_t off = (uint32_t)(r * 128 + c * 16);
            off ^= (off >> 3) & 0x70;
            const long long ga = (long long)r * K2 + kc * 64 + c * 8;
            cp16(base + A_HI + off, Ah + ga);
            cp16(base + A_LO + off, Al + ga);
        }
        {
            int r = tid >> 3, c = tid & 7;
            uint32_t off = (uint32_t)(r * 128 + c * 16);
            off ^= (off >> 3) & 0x70;
            const long long gb = (long long)r * K2 + kc * 64 + c * 8;
            cp16(base + B_HI + off, Bh + gb);
            cp16(base + B_LO + off, Bl + gb);
        }
    };

    load(0, 0);
    CP_COMMIT();

    for (int kc = 0; kc < K2 / 64; kc++) {
        if (kc + 1 < K2 / 64) {
            load(kc + 1, (kc + 1) & 1);
            CP_COMMIT();
            CP_WAIT(1);
        } else {
            CP_WAIT(0);
        }
        __syncthreads();

        const uint32_t base = sb + (kc & 1) * STGF;
#pragma unroll
        for (int ks = 0; ks < 4; ks++) {
            uint32_t ah[2][4], al[2][4], bh[2][2], bl[2][2];
            const uint32_t kbyte = ks * 32 + (lane >> 4) * 16;
#pragma unroll
            for (int mf = 0; mf < 2; mf++) {
                uint32_t row = wm * 32 + mf * 16 + (lane & 15);
                uint32_t off = row * 128 + kbyte;
                off ^= (off >> 3) & 0x70;
                ldsm4(ah[mf], base + A_HI + off);
                ldsm4(al[mf], base + A_LO + off);
            }
            {
                uint32_t row = wn * 16 + (lane >> 4) * 8 + (lane & 7);
                uint32_t kb = ks * 32 + ((lane >> 3) & 1) * 16;
                uint32_t off = row * 128 + kb;
                off ^= (off >> 3) & 0x70;
                uint32_t t[4];
                ldsm4(t, base + B_HI + off);
                bh[0][0] = t[0]; bh[0][1] = t[1];
                bh[1][0] = t[2]; bh[1][1] = t[3];
                ldsm4(t, base + B_LO + off);
                bl[0][0] = t[0]; bl[0][1] = t[1];
                bl[1][0] = t[2]; bl[1][1] = t[3];
            }
#pragma unroll
            for (int mf = 0; mf < 2; mf++)
#pragma unroll
                for (int nf = 0; nf < 2; nf++) mma_bf16(acc[mf][nf], ah[mf], bh[nf]);
#pragma unroll
            for (int mf = 0; mf < 2; mf++)
#pragma unroll
                for (int nf = 0; nf < 2; nf++) mma_bf16(acc[mf][nf], ah[mf], bl[nf]);
#pragma unroll
            for (int mf = 0; mf < 2; mf++)
#pragma unroll
                for (int nf = 0; nf < 2; nf++) mma_bf16(acc[mf][nf], al[mf], bh[nf]);
        }
        __syncthreads();
    }

    // epilogue: add bias, write out[b][co][v] for v < 25
    const int rr = lane >> 2, cc2 = (lane & 3) * 2;
    float* ob = out + (long long)b * (CC * VQ);
#pragma unroll
    for (int mf = 0; mf < 2; mf++) {
        const int row0 = co0 + wm * 32 + mf * 16 + rr;
        const float b0 = pb[row0], b1 = pb[row0 + 8];
#pragma unroll
        for (int nf = 0; nf < 2; nf++) {
            const int v0 = wn * 16 + nf * 8 + cc2;
            if (v0 < VQ)     ob[row0 * VQ + v0]           = acc[mf][nf][0] + b0;
            if (v0 + 1 < VQ) ob[row0 * VQ + v0 + 1]       = acc[mf][nf][1] + b0;
            if (v0 < VQ)     ob[(row0 + 8) * VQ + v0]     = acc[mf][nf][2] + b1;
            if (v0 + 1 < VQ) ob[(row0 + 8) * VQ + v0 + 1] = acc[mf][nf][3] + b1;
        }
    }
}

// ==================== fused prologue: qeff | weff | convx (blockIdx dispatch) =========
__global__ __launch_bounds__(256)
void pre_fused(const float* __restrict__ x_cls, const float* __restrict__ qw,
               const float* __restrict__ kw, const float* __restrict__ temp,
               const float* __restrict__ pw, const float* __restrict__ vw,
               const float* __restrict__ xp) {
    __shared__ float buf[6528];
    const int bx = blockIdx.x, t = threadIdx.x;

    if (bx < BB) {
        // ---- qeff: effective Q rows (bf16 hi/lo); pad rows never written ----
        const int b = bx;
        for (int i = t; i < CC * VQ; i += 256) buf[i] = x_cls[b * CC * VQ + i];
        __syncthreads();

        float acc[VQ];
#pragma unroll
        for (int v = 0; v < VQ; v++) acc[v] = 0.f;
        const float* wrow = qw + t * CC;
        for (int c2 = 0; c2 < CC; c2++) {
            float w = wrow[c2];
#pragma unroll
            for (int v = 0; v < VQ; v++) acc[v] += w * buf[c2 * VQ + v];
        }
        const float s = temp[t >> 5] * 0.17677669529663687f;
        __syncthreads();
#pragma unroll
        for (int v = 0; v < VQ; v++) buf[v * 260 + t] = acc[v] * s;
        __syncthreads();

        for (int h = 0; h < HH; h++) {
            float kv[HD];
#pragma unroll
            for (int d = 0; d < HD; d++) kv[d] = kw[(h * HD + d) * CC + t];
            for (int v = 0; v < VQ; v++) {
                float a = 0.f;
#pragma unroll
                for (int d = 0; d < HD; d++) a += buf[v * 260 + h * HD + d] * kv[d];
                bf hi, lo; split_bf(a, hi, lo);
                const long long idx = ((long long)b * RP + h * VQ + v) * CC + t;
                g_Qeh[idx] = hi;
                g_Qel[idx] = lo;
            }
        }
    } else if (bx < 2 * BB) {
        // ---- weff: We2[co][h*256+c] = sum_d pw[co][h*32+d]*vw[h*32+d][c], bf16 split ----
        const int idx = bx - BB;
        const int h = idx >> 3, co0 = (idx & 7) * 32, c = t;
        float vv[HD];
#pragma unroll
        for (int d = 0; d < HD; d++) vv[d] = vw[(h * HD + d) * CC + c];
        for (int i = 0; i < 32; i++) {
            const int co = co0 + i;
            float a = 0.f;
#pragma unroll
            for (int d = 0; d < HD; d++) a += pw[co * CC + h * HD + d] * vv[d];
            bf hi, lo; split_bf(a, hi, lo);
            const long long o = (long long)co * K2 + h * CC + c;
            g_We2h[o] = hi;
            g_We2l[o] = lo;
        }
    } else {
        // ---- convx: streaming split of x_patch into bf16 hi/lo ----
        const long long i = ((long long)(bx - 2 * BB) * 256 + t) * 4;
        float4 v = *(const float4*)(xp + i);
        bf h0, l0, h1, l1, h2, l2, h3, l3;
        split_bf(v.x, h0, l0); split_bf(v.y, h1, l1);
        split_bf(v.z, h2, l2); split_bf(v.w, h3, l3);
        __nv_bfloat162* ph = (__nv_bfloat162*)(g_Xh + i);
        __nv_bfloat162* pl = (__nv_bfloat162*)(g_Xl + i);
        ph[0] = __nv_bfloat162(h0, h1); ph[1] = __nv_bfloat162(h2, h3);
        pl[0] = __nv_bfloat162(l0, l1); pl[1] = __nv_bfloat162(l2, l3);
    }
}

// Row softmax over g_S rows r<200; emit bf16 hi/lo probabilities.
__global__ __launch_bounds__(256)
void softmax_kernel() {
    const int wid = threadIdx.x >> 5, lane = threadIdx.x & 31;
    const int r = blockIdx.x * 8 + wid, b = blockIdx.y;
    const float* p = g_S + ((long long)b * RP + r) * NTOK;

    float v[50];
    float mx = -1e30f;
#pragma unroll
    for (int i = 0; i < 50; i++) { v[i] = p[i * 32 + lane]; mx = fmaxf(mx, v[i]); }
#pragma unroll
    for (int o = 16; o; o >>= 1) mx = fmaxf(mx, __shfl_xor_sync(0xffffffffu, mx, o));
    float s = 0.f;
#pragma unroll
    for (int i = 0; i < 50; i++) { float e = __expf(v[i] - mx); v[i] = e; s += e; }
#pragma unroll
    for (int o = 16; o; o >>= 1) s += __shfl_xor_sync(0xffffffffu, s, o);
    const float inv = 1.f / s;

    bf* ph = g_Ph + ((long long)b * RP + r) * NTOK;
    bf* pl = g_Pl + ((long long)b * RP + r) * NTOK;
#pragma unroll
    for (int i = 0; i < 50; i++) {
        bf hi, lo; split_bf(v[i] * inv, hi, lo);
        ph[i * 32 + lane] = hi;
        pl[i * 32 + lane] = lo;
    }
}

// ---------------------------------------------------------------
extern "C" void kernel_launch(void* const* d_in, const int* in_sizes, int n_in,
                              void* d_out, int out_size) {
    (void)in_sizes; (void)n_in; (void)out_size;
    const float* x_cls   = (const float*)d_in[0];
    const float* x_patch = (const float*)d_in[1];
    const float* q_w     = (const float*)d_in[2];
    const float* k_w     = (const float*)d_in[3];
    const float* v_w     = (const float*)d_in[4];
    const float* temp    = (const float*)d_in[5];
    const float* proj_w  = (const float*)d_in[6];
    const float* proj_b  = (const float*)d_in[7];
    float* out = (float*)d_out;

    const int SMEM1 = 2 * STG1;   // 102400
    const int SMEM2 = 2 * STG2;   // 98304
    const int SMEMF = 2 * STGF;   // 81920
    cudaFuncSetAttribute(gemm1_mma, cudaFuncAttributeMaxDynamicSharedMemorySize, SMEM1);
    cudaFuncSetAttribute(gemm2_mma, cudaFuncAttributeMaxDynamicSharedMemorySize, SMEM2);
    cudaFuncSetAttribute(final_mma, cudaFuncAttributeMaxDynamicSharedMemorySize, SMEMF);

    const int convx_blocks = (BB * CC * NTOK) / 1024;
    pre_fused<<<2 * BB + convx_blocks, 256>>>(x_cls, q_w, k_w, temp,
                                              proj_w, v_w, x_patch);
    gemm1_mma<<<dim3(NTOK / 64, 2, BB), 256, SMEM1>>>();
    softmax_kernel<<<dim3(RR / 8, BB), 256>>>();
    gemm2_mma<<<dim3(4, 2 * KSPL, BB), 256, SMEM2>>>();
    reduce_yt<<<dim3(RR, BB), 256>>>();
    final_mma<<<dim3(2, 1, BB), 256, SMEMF>>>(proj_b, out);
}